// round 13
// baseline (speedup 1.0000x reference)
#include <cuda_runtime.h>
#include <cuda_bf16.h>
#include <cstdint>

// Problem constants (fixed by the reference)
constexpr int N_NODES = 100000;
constexpr int N_EDGES = 640000;
constexpr int D       = 128;

constexpr int SCAN_B  = 256;
constexpr int NBLK    = (N_NODES + SCAN_B - 1) / SCAN_B;   // 391

// ---------------------------------------------------------------------------
// Scratch (allocation-free: __device__ globals)
// ---------------------------------------------------------------------------
__device__ int   g_ideg_out[N_NODES];
__device__ int   g_ideg_in [N_NODES];
__device__ float g_inv_out[N_NODES];
__device__ float g_inv_in [N_NODES];
__device__ int   g_off   [N_NODES + 1];   // CSR row offsets (by dst)
__device__ int   g_cursor[N_NODES];
__device__ int   g_csr   [N_EDGES];       // src indices grouped by dst
__device__ int   g_bsum  [512];           // scan partials
__device__ float g_h1 [(size_t)N_NODES * D];   // layer-1 activations (fp32)
// W split to bf16 hi/lo, stored TRANSPOSED: [n][k]
__device__ __nv_bfloat16 g_whiT[2][D * D];
__device__ __nv_bfloat16 g_wloT[2][D * D];

// ---------------------------------------------------------------------------
// Fused init (zero degree counters) + W pre-split (independent index ranges)
// ---------------------------------------------------------------------------
__global__ void init_convert_kernel(const float* __restrict__ W1,
                                    const float* __restrict__ W2) {
    int i = blockIdx.x * blockDim.x + threadIdx.x;
    if (i < N_NODES) { g_ideg_out[i] = 0; g_ideg_in[i] = 0; }
    if (i < 2 * D * D) {
        int layer = i >> 14;
        int r     = i & (D * D - 1);
        int k = r >> 7;
        int n = r & (D - 1);
        const float* W = layer ? W2 : W1;
        float w = W[k * D + n];
        __nv_bfloat16 hi = __float2bfloat16(w);
        float lo = w - __bfloat162float(hi);
        g_whiT[layer][n * D + k] = hi;
        g_wloT[layer][n * D + k] = __float2bfloat16(lo);
    }
}

__global__ void degree_kernel(const int* __restrict__ src,
                              const int* __restrict__ dst) {
    int i = blockIdx.x * blockDim.x + threadIdx.x;
    if (i < N_EDGES) {
        atomicAdd(&g_ideg_out[src[i]], 1);
        atomicAdd(&g_ideg_in [dst[i]], 1);
    }
}

// ---------------------------------------------------------------------------
// Block scan of in-degrees (shuffle-based) + fused inv-sqrt computation
// ---------------------------------------------------------------------------
__global__ void scan_block_kernel() {
    int tid  = threadIdx.x;
    int i    = blockIdx.x * SCAN_B + tid;
    int lane = tid & 31;
    int wid  = tid >> 5;

    int v = (i < N_NODES) ? g_ideg_in[i] : 0;
    if (i < N_NODES) {
        g_inv_out[i] = rsqrtf((float)max(g_ideg_out[i], 1));
        g_inv_in [i] = rsqrtf((float)max(v, 1));
    }

    int x = v;
    #pragma unroll
    for (int o = 1; o < 32; o <<= 1) {
        int t = __shfl_up_sync(0xffffffffu, x, o);
        if (lane >= o) x += t;
    }
    __shared__ int wsum[8];
    if (lane == 31) wsum[wid] = x;
    __syncthreads();
    if (wid == 0 && lane < 8) {
        int y = wsum[lane];
        #pragma unroll
        for (int o = 1; o < 8; o <<= 1) {
            int t = __shfl_up_sync(0xffu, y, o);
            if (lane >= o) y += t;
        }
        wsum[lane] = y;
    }
    __syncthreads();
    int base = wid ? wsum[wid - 1] : 0;
    int incl = x + base;
    if (i < N_NODES) g_off[i] = incl - v;          // exclusive within block
    if (tid == SCAN_B - 1) g_bsum[blockIdx.x] = incl;
}

// ---------------------------------------------------------------------------
// Fused scan finish: every block redundantly scans the 391 partials in smem
// (cheap), then applies its base to its 512 offsets + cursor init.
// Grid: ceil(N/512) x 512 threads.
// ---------------------------------------------------------------------------
__global__ void scan_finish_kernel() {
    __shared__ int excl[512];
    int tid  = threadIdx.x;
    int lane = tid & 31;
    int wid  = tid >> 5;          // 16 warps

    int v = (tid < NBLK) ? g_bsum[tid] : 0;
    int x = v;
    #pragma unroll
    for (int o = 1; o < 32; o <<= 1) {
        int t = __shfl_up_sync(0xffffffffu, x, o);
        if (lane >= o) x += t;
    }
    __shared__ int ws[16];
    if (lane == 31) ws[wid] = x;
    __syncthreads();
    if (wid == 0 && lane < 16) {
        int y = ws[lane];
        #pragma unroll
        for (int o = 1; o < 16; o <<= 1) {
            int t = __shfl_up_sync(0xffffu, y, o);
            if (lane >= o) y += t;
        }
        ws[lane] = y;
    }
    __syncthreads();
    int base = wid ? ws[wid - 1] : 0;
    excl[tid] = x + base - v;    // exclusive block bases
    __syncthreads();

    int i = blockIdx.x * 512 + tid;
    if (i < N_NODES) {
        int o = g_off[i] + excl[i >> 8];
        g_off[i]    = o;
        g_cursor[i] = o;
    }
    if (i == 0) g_off[N_NODES] = N_EDGES;
}

__global__ void fill_csr_kernel(const int* __restrict__ src,
                                const int* __restrict__ dst) {
    int e = blockIdx.x * blockDim.x + threadIdx.x;
    if (e < N_EDGES) {
        int p = atomicAdd(&g_cursor[dst[e]], 1);
        g_csr[p] = src[e];
    }
}

// ---------------------------------------------------------------------------
// Fused aggregate + tensor-core GEMM:
//   out[row] = relu?( (inv_in[row] * sum_{s in in(row)} inv_out[s]*x[s]) @ W + b )
// Phase 1: each warp pull-aggregates 16 of the CTA's 128 rows into smem,
//          split to bf16 hi/lo (A operand). B chunk prefetches (cp.async)
//          are issued before the gather so W staging is hidden.
// Phase 2: 4x k32-chunk mma loop, B double-buffered, 3-product bf16 emulation.
// CTA 128x128, 256 thr, smem 108.5KB -> 2 CTAs/SM.
// ---------------------------------------------------------------------------
__device__ __forceinline__ void mma_bf16(float* c, const uint32_t* a, const uint32_t* b) {
    asm volatile(
        "mma.sync.aligned.m16n8k16.row.col.f32.bf16.bf16.f32 "
        "{%0,%1,%2,%3}, {%4,%5,%6,%7}, {%8,%9}, {%0,%1,%2,%3};\n"
        : "+f"(c[0]), "+f"(c[1]), "+f"(c[2]), "+f"(c[3])
        : "r"(a[0]), "r"(a[1]), "r"(a[2]), "r"(a[3]), "r"(b[0]), "r"(b[1]));
}

__device__ __forceinline__ void cp16(uint32_t smem, const void* gptr) {
    asm volatile("cp.async.ca.shared.global [%0], [%1], 16;\n"
                 :: "r"(smem), "l"(gptr));
}

constexpr int LDSA = 132;  // A smem stride (bf16): 66 words, 8 rows conflict-free
constexpr int LDSB = 40;   // B smem stride (bf16): 20 words, conflict-free
constexpr int A_ELEMS = 128 * LDSA;          // 16896 per matrix
constexpr int B_ELEMS = 128 * LDSB;          // 5120 per matrix per stage
constexpr int SMEM_BYTES = (2 * A_ELEMS + 4 * B_ELEMS) * 2;   // 108,544

__global__ void __launch_bounds__(256, 2)
agg_gemm_kernel(const float* __restrict__ x, int layer,
                const float* __restrict__ bias,
                float* __restrict__ out, int relu) {
    extern __shared__ __align__(16) __nv_bfloat16 smem[];
    __nv_bfloat16* Ahi = smem;                 // [128][LDSA]
    __nv_bfloat16* Alo = smem + A_ELEMS;       // [128][LDSA]
    __nv_bfloat16* Bst = smem + 2 * A_ELEMS;   // [2 stages][2 mats][128][LDSB]

    const int t    = threadIdx.x;
    const int lane = t & 31;
    const int w    = t >> 5;
    const int wr   = w >> 1;
    const int wc   = w & 1;
    const int row0 = blockIdx.x * 128;

    const __nv_bfloat16* WhiT = g_whiT[layer];
    const __nv_bfloat16* WloT = g_wloT[layer];

    // stage B chunk c (k = c*32..c*32+31) into stage s
    auto stage_b = [&](int c, int s) {
        const int kc = c * 32;
        __nv_bfloat16* dsth = Bst + (s * 2 + 0) * B_ELEMS;
        __nv_bfloat16* dstl = Bst + (s * 2 + 1) * B_ELEMS;
        #pragma unroll
        for (int j = 0; j < 2; j++) {
            int idx = t + 256 * j;        // 0..511
            int n   = idx >> 2;           // 0..127
            int k8  = (idx & 3) * 8;      // 0,8,16,24
            uint32_t so = (uint32_t)((n * LDSB + k8) * 2);
            cp16((uint32_t)__cvta_generic_to_shared(dsth) + so, WhiT + n * D + kc + k8);
            cp16((uint32_t)__cvta_generic_to_shared(dstl) + so, WloT + n * D + kc + k8);
        }
        asm volatile("cp.async.commit_group;\n");
    };

    // Issue both B prefetch stages up-front: they land during the gather.
    stage_b(0, 0);
    stage_b(1, 1);

    // ---- Phase 1: aggregate this CTA's 128 rows into smem A (bf16 hi/lo) ----
    {
        const int c4 = lane * 4;
        for (int rr = 0; rr < 16; rr++) {
            int r  = w * 16 + rr;
            int gr = row0 + r;
            float ax = 0.f, ay = 0.f, az = 0.f, aw = 0.f;
            if (gr < N_NODES) {
                int beg = g_off[gr];
                int end = g_off[gr + 1];
                int e   = beg;
                int n4  = beg + ((end - beg) & ~3);
                for (; e < n4; e += 4) {
                    int s0 = g_csr[e];
                    int s1 = g_csr[e + 1];
                    int s2 = g_csr[e + 2];
                    int s3 = g_csr[e + 3];
                    float c0 = g_inv_out[s0];
                    float c1 = g_inv_out[s1];
                    float c2 = g_inv_out[s2];
                    float c3 = g_inv_out[s3];
                    float4 v0 = *reinterpret_cast<const float4*>(x + (size_t)s0 * D + c4);
                    float4 v1 = *reinterpret_cast<const float4*>(x + (size_t)s1 * D + c4);
                    float4 v2 = *reinterpret_cast<const float4*>(x + (size_t)s2 * D + c4);
                    float4 v3 = *reinterpret_cast<const float4*>(x + (size_t)s3 * D + c4);
                    ax += v0.x * c0 + v1.x * c1 + v2.x * c2 + v3.x * c3;
                    ay += v0.y * c0 + v1.y * c1 + v2.y * c2 + v3.y * c3;
                    az += v0.z * c0 + v1.z * c1 + v2.z * c2 + v3.z * c3;
                    aw += v0.w * c0 + v1.w * c1 + v2.w * c2 + v3.w * c3;
                }
                for (; e < end; e++) {
                    int   s0 = g_csr[e];
                    float c0 = g_inv_out[s0];
                    float4 v0 = *reinterpret_cast<const float4*>(x + (size_t)s0 * D + c4);
                    ax += v0.x * c0; ay += v0.y * c0; az += v0.z * c0; aw += v0.w * c0;
                }
                float si = g_inv_in[gr];
                ax *= si; ay *= si; az *= si; aw *= si;
            }
            __nv_bfloat162 h01, h23, l01, l23;
            h01.x = __float2bfloat16(ax); h01.y = __float2bfloat16(ay);
            h23.x = __float2bfloat16(az); h23.y = __float2bfloat16(aw);
            l01.x = __float2bfloat16(ax - __bfloat162float(h01.x));
            l01.y = __float2bfloat16(ay - __bfloat162float(h01.y));
            l23.x = __float2bfloat16(az - __bfloat162float(h23.x));
            l23.y = __float2bfloat16(aw - __bfloat162float(h23.y));
            *reinterpret_cast<__nv_bfloat162*>(&Ahi[r * LDSA + c4])     = h01;
            *reinterpret_cast<__nv_bfloat162*>(&Ahi[r * LDSA + c4 + 2]) = h23;
            *reinterpret_cast<__nv_bfloat162*>(&Alo[r * LDSA + c4])     = l01;
            *reinterpret_cast<__nv_bfloat162*>(&Alo[r * LDSA + c4 + 2]) = l23;
        }
    }
    __syncthreads();

    // ---- Phase 2: mma loop over 4 k32 chunks ----
    float acc[2][8][4];
    #pragma unroll
    for (int mt = 0; mt < 2; mt++)
        #pragma unroll
        for (int nt = 0; nt < 8; nt++)
            #pragma unroll
            for (int r = 0; r < 4; r++) acc[mt][nt][r] = 0.0f;

    const int l4 = lane >> 2;
    const int l2 = (lane & 3) * 2;

    #pragma unroll
    for (int c = 0; c < 4; c++) {
        const int s = c & 1;
        if (c < 3) asm volatile("cp.async.wait_group 1;\n");
        else       asm volatile("cp.async.wait_group 0;\n");
        __syncthreads();

        const int kc = c * 32;
        const __nv_bfloat16* Bshi = Bst + (s * 2 + 0) * B_ELEMS;
        const __nv_bfloat16* Bslo = Bst + (s * 2 + 1) * B_ELEMS;

        #pragma unroll
        for (int kk = 0; kk < 32; kk += 16) {
            uint32_t afh[2][4], afl[2][4];
            #pragma unroll
            for (int mt = 0; mt < 2; mt++) {
                int ar = wr * 32 + mt * 16;
                int k0 = kc + kk + l2;
                afh[mt][0] = *reinterpret_cast<const uint32_t*>(&Ahi[(ar + l4)     * LDSA + k0]);
                afh[mt][1] = *reinterpret_cast<const uint32_t*>(&Ahi[(ar + l4 + 8) * LDSA + k0]);
                afh[mt][2] = *reinterpret_cast<const uint32_t*>(&Ahi[(ar + l4)     * LDSA + k0 + 8]);
                afh[mt][3] = *reinterpret_cast<const uint32_t*>(&Ahi[(ar + l4 + 8) * LDSA + k0 + 8]);
                afl[mt][0] = *reinterpret_cast<const uint32_t*>(&Alo[(ar + l4)     * LDSA + k0]);
                afl[mt][1] = *reinterpret_cast<const uint32_t*>(&Alo[(ar + l4 + 8) * LDSA + k0]);
                afl[mt][2] = *reinterpret_cast<const uint32_t*>(&Alo[(ar + l4)     * LDSA + k0 + 8]);
                afl[mt][3] = *reinterpret_cast<const uint32_t*>(&Alo[(ar + l4 + 8) * LDSA + k0 + 8]);
            }
            #pragma unroll
            for (int nt = 0; nt < 8; nt++) {
                int bn = wc * 64 + nt * 8 + l4;
                int k0 = kk + l2;
                uint32_t bfh[2], bfl[2];
                bfh[0] = *reinterpret_cast<const uint32_t*>(&Bshi[bn * LDSB + k0]);
                bfh[1] = *reinterpret_cast<const uint32_t*>(&Bshi[bn * LDSB + k0 + 8]);
                bfl[0] = *reinterpret_cast<const uint32_t*>(&Bslo[bn * LDSB + k0]);
                bfl[1] = *reinterpret_cast<const uint32_t*>(&Bslo[bn * LDSB + k0 + 8]);
                #pragma unroll
                for (int mt = 0; mt < 2; mt++) {
                    mma_bf16(acc[mt][nt], afh[mt], bfh);
                    mma_bf16(acc[mt][nt], afh[mt], bfl);
                    mma_bf16(acc[mt][nt], afl[mt], bfh);
                }
            }
        }
        __syncthreads();
        if (c < 2) stage_b(c + 2, s);
    }

    // ---- epilogue: + bias, relu, store ----
    #pragma unroll
    for (int mt = 0; mt < 2; mt++) {
        int gr0 = row0 + wr * 32 + mt * 16 + l4;
        int gr1 = gr0 + 8;
        #pragma unroll
        for (int nt = 0; nt < 8; nt++) {
            int col = wc * 64 + nt * 8 + l2;
            float2 bb = *reinterpret_cast<const float2*>(bias + col);
            float o0 = acc[mt][nt][0] + bb.x;
            float o1 = acc[mt][nt][1] + bb.y;
            float o2 = acc[mt][nt][2] + bb.x;
            float o3 = acc[mt][nt][3] + bb.y;
            if (relu) {
                o0 = fmaxf(o0, 0.f); o1 = fmaxf(o1, 0.f);
                o2 = fmaxf(o2, 0.f); o3 = fmaxf(o3, 0.f);
            }
            if (gr0 < N_NODES)
                *reinterpret_cast<float2*>(out + (size_t)gr0 * D + col) = make_float2(o0, o1);
            if (gr1 < N_NODES)
                *reinterpret_cast<float2*>(out + (size_t)gr1 * D + col) = make_float2(o2, o3);
        }
    }
}

// ---------------------------------------------------------------------------
// Launch sequence (graph-capturable)
// Inputs (metadata order): t, h, src, dst, W1, b1, W2, b2
// ---------------------------------------------------------------------------
extern "C" void kernel_launch(void* const* d_in, const int* in_sizes, int n_in,
                              void* d_out, int out_size) {
    const float* h   = (const float*)d_in[1];
    const int*   src = (const int*)  d_in[2];
    const int*   dst = (const int*)  d_in[3];
    const float* W1  = (const float*)d_in[4];
    const float* b1  = (const float*)d_in[5];
    const float* W2  = (const float*)d_in[6];
    const float* b2  = (const float*)d_in[7];
    float* out = (float*)d_out;

    static float* p_h1 = nullptr;
    if (!p_h1) {
        void* ph = nullptr;
        cudaGetSymbolAddress(&ph, g_h1);
        p_h1 = (float*)ph;
        cudaFuncSetAttribute(agg_gemm_kernel,
                             cudaFuncAttributeMaxDynamicSharedMemorySize,
                             SMEM_BYTES);
    }

    const int TB = 256;
    const int blocks_nodes = (N_NODES + TB - 1) / TB;      // 391
    const int blocks_edges = (N_EDGES + TB - 1) / TB;      // 2500
    const int blocks_fin   = (N_NODES + 511) / 512;        // 196
    const int blocks_gemm  = (N_NODES + 127) / 128;        // 782

    // preprocessing: 5 launches
    init_convert_kernel<<<blocks_nodes, TB>>>(W1, W2);
    degree_kernel<<<blocks_edges, TB>>>(src, dst);
    scan_block_kernel<<<NBLK, SCAN_B>>>();
    scan_finish_kernel<<<blocks_fin, 512>>>();
    fill_csr_kernel<<<blocks_edges, TB>>>(src, dst);

    // layer 1 (fused aggregate + GEMM)
    agg_gemm_kernel<<<blocks_gemm, TB, SMEM_BYTES>>>(h, 0, b1, p_h1, /*relu=*/1);
    // layer 2
    agg_gemm_kernel<<<blocks_gemm, TB, SMEM_BYTES>>>(p_h1, 1, b2, out, /*relu=*/0);
}

// round 14
// speedup vs baseline: 1.2338x; 1.2338x over previous
#include <cuda_runtime.h>
#include <cuda_bf16.h>
#include <cstdint>

// Problem constants (fixed by the reference)
constexpr int N_NODES = 100000;
constexpr int N_EDGES = 640000;
constexpr int D       = 128;

constexpr int SCAN_B  = 256;
constexpr int NBLK    = (N_NODES + SCAN_B - 1) / SCAN_B;   // 391

// ---------------------------------------------------------------------------
// Scratch (allocation-free: __device__ globals)
// ---------------------------------------------------------------------------
__device__ int   g_ideg_out[N_NODES];
__device__ int   g_ideg_in [N_NODES];
__device__ float g_inv_out[N_NODES];
__device__ float g_inv_in [N_NODES];
__device__ int   g_off   [N_NODES + 1];   // CSR row offsets (by dst)
__device__ int   g_cursor[N_NODES];
__device__ int   g_csr   [N_EDGES];       // src indices grouped by dst
__device__ int   g_bsum  [512];           // scan partials
// Aggregation result, pre-split to bf16 hi/lo (GEMM A operand)
__device__ __nv_bfloat16 g_ahi[(size_t)N_NODES * D];
__device__ __nv_bfloat16 g_alo[(size_t)N_NODES * D];
__device__ float g_h1 [(size_t)N_NODES * D];   // layer-1 activations (fp32)
// W split to bf16 hi/lo, stored TRANSPOSED: [n][k]
__device__ __nv_bfloat16 g_whiT[2][D * D];
__device__ __nv_bfloat16 g_wloT[2][D * D];

// ---------------------------------------------------------------------------
// Fused init (zero degree counters) + W pre-split (independent index ranges)
// ---------------------------------------------------------------------------
__global__ void init_convert_kernel(const float* __restrict__ W1,
                                    const float* __restrict__ W2) {
    int i = blockIdx.x * blockDim.x + threadIdx.x;
    if (i < N_NODES) { g_ideg_out[i] = 0; g_ideg_in[i] = 0; }
    if (i < 2 * D * D) {
        int layer = i >> 14;
        int r     = i & (D * D - 1);
        int k = r >> 7;
        int n = r & (D - 1);
        const float* W = layer ? W2 : W1;
        float w = W[k * D + n];
        __nv_bfloat16 hi = __float2bfloat16(w);
        float lo = w - __bfloat162float(hi);
        g_whiT[layer][n * D + k] = hi;
        g_wloT[layer][n * D + k] = __float2bfloat16(lo);
    }
}

__global__ void degree_kernel(const int* __restrict__ src,
                              const int* __restrict__ dst) {
    int i = blockIdx.x * blockDim.x + threadIdx.x;
    if (i < N_EDGES) {
        atomicAdd(&g_ideg_out[src[i]], 1);
        atomicAdd(&g_ideg_in [dst[i]], 1);
    }
}

// ---------------------------------------------------------------------------
// Block scan of in-degrees (shuffle-based) + fused inv-sqrt computation
// ---------------------------------------------------------------------------
__global__ void scan_block_kernel() {
    int tid  = threadIdx.x;
    int i    = blockIdx.x * SCAN_B + tid;
    int lane = tid & 31;
    int wid  = tid >> 5;

    int v = (i < N_NODES) ? g_ideg_in[i] : 0;
    if (i < N_NODES) {
        g_inv_out[i] = rsqrtf((float)max(g_ideg_out[i], 1));
        g_inv_in [i] = rsqrtf((float)max(v, 1));
    }

    int x = v;
    #pragma unroll
    for (int o = 1; o < 32; o <<= 1) {
        int t = __shfl_up_sync(0xffffffffu, x, o);
        if (lane >= o) x += t;
    }
    __shared__ int wsum[8];
    if (lane == 31) wsum[wid] = x;
    __syncthreads();
    if (wid == 0 && lane < 8) {
        int y = wsum[lane];
        #pragma unroll
        for (int o = 1; o < 8; o <<= 1) {
            int t = __shfl_up_sync(0xffu, y, o);
            if (lane >= o) y += t;
        }
        wsum[lane] = y;
    }
    __syncthreads();
    int base = wid ? wsum[wid - 1] : 0;
    int incl = x + base;
    if (i < N_NODES) g_off[i] = incl - v;          // exclusive within block
    if (tid == SCAN_B - 1) g_bsum[blockIdx.x] = incl;
}

// ---------------------------------------------------------------------------
// Fused scan finish: every block redundantly scans the 391 partials in smem,
// then applies its base to its 512 offsets + cursor init.
// ---------------------------------------------------------------------------
__global__ void scan_finish_kernel() {
    __shared__ int excl[512];
    int tid  = threadIdx.x;
    int lane = tid & 31;
    int wid  = tid >> 5;          // 16 warps

    int v = (tid < NBLK) ? g_bsum[tid] : 0;
    int x = v;
    #pragma unroll
    for (int o = 1; o < 32; o <<= 1) {
        int t = __shfl_up_sync(0xffffffffu, x, o);
        if (lane >= o) x += t;
    }
    __shared__ int ws[16];
    if (lane == 31) ws[wid] = x;
    __syncthreads();
    if (wid == 0 && lane < 16) {
        int y = ws[lane];
        #pragma unroll
        for (int o = 1; o < 16; o <<= 1) {
            int t = __shfl_up_sync(0xffffu, y, o);
            if (lane >= o) y += t;
        }
        ws[lane] = y;
    }
    __syncthreads();
    int base = wid ? ws[wid - 1] : 0;
    excl[tid] = x + base - v;    // exclusive block bases
    __syncthreads();

    int i = blockIdx.x * 512 + tid;
    if (i < N_NODES) {
        int o = g_off[i] + excl[i >> 8];
        g_off[i]    = o;
        g_cursor[i] = o;
    }
    if (i == 0) g_off[N_NODES] = N_EDGES;
}

__global__ void fill_csr_kernel(const int* __restrict__ src,
                                const int* __restrict__ dst) {
    int e = blockIdx.x * blockDim.x + threadIdx.x;
    if (e < N_EDGES) {
        int p = atomicAdd(&g_cursor[dst[e]], 1);
        g_csr[p] = src[e];
    }
}

// ---------------------------------------------------------------------------
// Pull aggregation: a[n] = inv_in[n] * sum_{s in in(n)} inv_out[s] * x[s]
// TWO warps per dst node (each owns a 64-feature half-row; float2 per lane):
// 200K warps in flight -> shorter serial chains, shorter degree tail.
// 4-way unrolled edge loop. Writes result pre-split to bf16 hi/lo.
// ---------------------------------------------------------------------------
__global__ void __launch_bounds__(256)
aggregate_kernel(const float* __restrict__ x) {
    int gw   = (blockIdx.x * blockDim.x + threadIdx.x) >> 5;
    int node = gw >> 1;
    int half = gw & 1;
    int lane = threadIdx.x & 31;
    if (node >= N_NODES) return;

    int beg = g_off[node];
    int end = g_off[node + 1];
    const int c2 = half * 64 + lane * 2;

    float ax = 0.f, ay = 0.f;
    int e  = beg;
    int n4 = beg + ((end - beg) & ~3);
    for (; e < n4; e += 4) {
        int s0 = g_csr[e];
        int s1 = g_csr[e + 1];
        int s2 = g_csr[e + 2];
        int s3 = g_csr[e + 3];
        float c0 = g_inv_out[s0];
        float c1 = g_inv_out[s1];
        float c2s = g_inv_out[s2];
        float c3 = g_inv_out[s3];
        float2 v0 = *reinterpret_cast<const float2*>(x + (size_t)s0 * D + c2);
        float2 v1 = *reinterpret_cast<const float2*>(x + (size_t)s1 * D + c2);
        float2 v2 = *reinterpret_cast<const float2*>(x + (size_t)s2 * D + c2);
        float2 v3 = *reinterpret_cast<const float2*>(x + (size_t)s3 * D + c2);
        ax += v0.x * c0 + v1.x * c1 + v2.x * c2s + v3.x * c3;
        ay += v0.y * c0 + v1.y * c1 + v2.y * c2s + v3.y * c3;
    }
    for (; e < end; e++) {
        int   s0 = g_csr[e];
        float c0 = g_inv_out[s0];
        float2 v0 = *reinterpret_cast<const float2*>(x + (size_t)s0 * D + c2);
        ax += v0.x * c0; ay += v0.y * c0;
    }

    float si = g_inv_in[node];
    ax *= si; ay *= si;

    __nv_bfloat162 h01, l01;
    h01.x = __float2bfloat16(ax);
    h01.y = __float2bfloat16(ay);
    l01.x = __float2bfloat16(ax - __bfloat162float(h01.x));
    l01.y = __float2bfloat16(ay - __bfloat162float(h01.y));

    *reinterpret_cast<uint32_t*>(g_ahi + (size_t)node * D + c2) =
        *reinterpret_cast<uint32_t*>(&h01);
    *reinterpret_cast<uint32_t*>(g_alo + (size_t)node * D + c2) =
        *reinterpret_cast<uint32_t*>(&l01);
}

// ---------------------------------------------------------------------------
// Tensor-core GEMM: out = relu?( A @ W + b ), A pre-split bf16 hi/lo.
// cp.async double-buffered staging. CTA 128x128, 256 thr, warp 32x64.
// 3-product bf16 emulation.
// ---------------------------------------------------------------------------
__device__ __forceinline__ void mma_bf16(float* c, const uint32_t* a, const uint32_t* b) {
    asm volatile(
        "mma.sync.aligned.m16n8k16.row.col.f32.bf16.bf16.f32 "
        "{%0,%1,%2,%3}, {%4,%5,%6,%7}, {%8,%9}, {%0,%1,%2,%3};\n"
        : "+f"(c[0]), "+f"(c[1]), "+f"(c[2]), "+f"(c[3])
        : "r"(a[0]), "r"(a[1]), "r"(a[2]), "r"(a[3]), "r"(b[0]), "r"(b[1]));
}

__device__ __forceinline__ void cp16(uint32_t smem, const void* gptr, int src_bytes) {
    asm volatile("cp.async.ca.shared.global [%0], [%1], 16, %2;\n"
                 :: "r"(smem), "l"(gptr), "r"(src_bytes));
}

constexpr int LDSB = 40;  // padded smem stride (bf16 units), conflict-free

__global__ void __launch_bounds__(256, 2)
gemm_tc_kernel(int layer, const float* __restrict__ bias,
               float* __restrict__ out, int relu) {
    // [stage][0=Ahi,1=Alo,2=Bhi,3=Blo]
    __shared__ __align__(16) __nv_bfloat16 sm[2][4][128 * LDSB];

    const int t    = threadIdx.x;
    const int lane = t & 31;
    const int w    = t >> 5;
    const int wr   = w >> 1;
    const int wc   = w & 1;
    const int row0 = blockIdx.x * 128;

    const __nv_bfloat16* WhiT = g_whiT[layer];
    const __nv_bfloat16* WloT = g_wloT[layer];

    auto stage_chunk = [&](int c, int s) {
        const int kc = c * 32;
        #pragma unroll
        for (int j = 0; j < 2; j++) {
            int idx = t + 256 * j;        // 0..511
            int r   = idx >> 2;           // 0..127
            int k8  = (idx & 3) * 8;      // 0,8,16,24
            int gr  = row0 + r;
            int ok  = (gr < N_NODES) ? 16 : 0;
            size_t ga = (size_t)min(gr, N_NODES - 1) * D + kc + k8;
            uint32_t so = (uint32_t)((r * LDSB + k8) * 2);
            cp16((uint32_t)__cvta_generic_to_shared(&sm[s][0][0]) + so, g_ahi + ga, ok);
            cp16((uint32_t)__cvta_generic_to_shared(&sm[s][1][0]) + so, g_alo + ga, ok);
            cp16((uint32_t)__cvta_generic_to_shared(&sm[s][2][0]) + so, WhiT + r * D + kc + k8, 16);
            cp16((uint32_t)__cvta_generic_to_shared(&sm[s][3][0]) + so, WloT + r * D + kc + k8, 16);
        }
        asm volatile("cp.async.commit_group;\n");
    };

    float acc[2][8][4];
    #pragma unroll
    for (int mt = 0; mt < 2; mt++)
        #pragma unroll
        for (int nt = 0; nt < 8; nt++)
            #pragma unroll
            for (int r = 0; r < 4; r++) acc[mt][nt][r] = 0.0f;

    const int l4 = lane >> 2;
    const int l2 = (lane & 3) * 2;

    stage_chunk(0, 0);
    stage_chunk(1, 1);

    #pragma unroll
    for (int c = 0; c < 4; c++) {
        const int s = c & 1;
        if (c < 3) asm volatile("cp.async.wait_group 1;\n");
        else       asm volatile("cp.async.wait_group 0;\n");
        __syncthreads();

        const __nv_bfloat16* Ashi = sm[s][0];
        const __nv_bfloat16* Aslo = sm[s][1];
        const __nv_bfloat16* Bshi = sm[s][2];
        const __nv_bfloat16* Bslo = sm[s][3];

        #pragma unroll
        for (int kk = 0; kk < 32; kk += 16) {
            uint32_t afh[2][4], afl[2][4];
            #pragma unroll
            for (int mt = 0; mt < 2; mt++) {
                int ar = wr * 32 + mt * 16;
                int k0 = kk + l2;
                afh[mt][0] = *reinterpret_cast<const uint32_t*>(&Ashi[(ar + l4)     * LDSB + k0]);
                afh[mt][1] = *reinterpret_cast<const uint32_t*>(&Ashi[(ar + l4 + 8) * LDSB + k0]);
                afh[mt][2] = *reinterpret_cast<const uint32_t*>(&Ashi[(ar + l4)     * LDSB + k0 + 8]);
                afh[mt][3] = *reinterpret_cast<const uint32_t*>(&Ashi[(ar + l4 + 8) * LDSB + k0 + 8]);
                afl[mt][0] = *reinterpret_cast<const uint32_t*>(&Aslo[(ar + l4)     * LDSB + k0]);
                afl[mt][1] = *reinterpret_cast<const uint32_t*>(&Aslo[(ar + l4 + 8) * LDSB + k0]);
                afl[mt][2] = *reinterpret_cast<const uint32_t*>(&Aslo[(ar + l4)     * LDSB + k0 + 8]);
                afl[mt][3] = *reinterpret_cast<const uint32_t*>(&Aslo[(ar + l4 + 8) * LDSB + k0 + 8]);
            }
            #pragma unroll
            for (int nt = 0; nt < 8; nt++) {
                int bn = wc * 64 + nt * 8 + l4;
                int k0 = kk + l2;
                uint32_t bfh[2], bfl[2];
                bfh[0] = *reinterpret_cast<const uint32_t*>(&Bshi[bn * LDSB + k0]);
                bfh[1] = *reinterpret_cast<const uint32_t*>(&Bshi[bn * LDSB + k0 + 8]);
                bfl[0] = *reinterpret_cast<const uint32_t*>(&Bslo[bn * LDSB + k0]);
                bfl[1] = *reinterpret_cast<const uint32_t*>(&Bslo[bn * LDSB + k0 + 8]);
                #pragma unroll
                for (int mt = 0; mt < 2; mt++) {
                    mma_bf16(acc[mt][nt], afh[mt], bfh);
                    mma_bf16(acc[mt][nt], afh[mt], bfl);
                    mma_bf16(acc[mt][nt], afl[mt], bfh);
                }
            }
        }
        __syncthreads();
        if (c < 2) stage_chunk(c + 2, s);
    }

    #pragma unroll
    for (int mt = 0; mt < 2; mt++) {
        int gr0 = row0 + wr * 32 + mt * 16 + l4;
        int gr1 = gr0 + 8;
        #pragma unroll
        for (int nt = 0; nt < 8; nt++) {
            int col = wc * 64 + nt * 8 + l2;
            float2 bb = *reinterpret_cast<const float2*>(bias + col);
            float o0 = acc[mt][nt][0] + bb.x;
            float o1 = acc[mt][nt][1] + bb.y;
            float o2 = acc[mt][nt][2] + bb.x;
            float o3 = acc[mt][nt][3] + bb.y;
            if (relu) {
                o0 = fmaxf(o0, 0.f); o1 = fmaxf(o1, 0.f);
                o2 = fmaxf(o2, 0.f); o3 = fmaxf(o3, 0.f);
            }
            if (gr0 < N_NODES)
                *reinterpret_cast<float2*>(out + (size_t)gr0 * D + col) = make_float2(o0, o1);
            if (gr1 < N_NODES)
                *reinterpret_cast<float2*>(out + (size_t)gr1 * D + col) = make_float2(o2, o3);
        }
    }
}

// ---------------------------------------------------------------------------
// Launch sequence (graph-capturable)
// Inputs (metadata order): t, h, src, dst, W1, b1, W2, b2
// ---------------------------------------------------------------------------
extern "C" void kernel_launch(void* const* d_in, const int* in_sizes, int n_in,
                              void* d_out, int out_size) {
    const float* h   = (const float*)d_in[1];
    const int*   src = (const int*)  d_in[2];
    const int*   dst = (const int*)  d_in[3];
    const float* W1  = (const float*)d_in[4];
    const float* b1  = (const float*)d_in[5];
    const float* W2  = (const float*)d_in[6];
    const float* b2  = (const float*)d_in[7];
    float* out = (float*)d_out;

    static float* p_h1 = nullptr;
    if (!p_h1) {
        void* ph = nullptr;
        cudaGetSymbolAddress(&ph, g_h1);
        p_h1 = (float*)ph;
    }

    const int TB = 256;
    const int blocks_nodes = (N_NODES + TB - 1) / TB;        // 391
    const int blocks_edges = (N_EDGES + TB - 1) / TB;        // 2500
    const int blocks_fin   = (N_NODES + 511) / 512;          // 196
    const int blocks_aggr  = (N_NODES * 64 + TB - 1) / TB;   // 2 warps/node
    const int blocks_gemm  = (N_NODES + 127) / 128;          // 782

    // preprocessing: 5 launches
    init_convert_kernel<<<blocks_nodes, TB>>>(W1, W2);
    degree_kernel<<<blocks_edges, TB>>>(src, dst);
    scan_block_kernel<<<NBLK, SCAN_B>>>();
    scan_finish_kernel<<<blocks_fin, 512>>>();
    fill_csr_kernel<<<blocks_edges, TB>>>(src, dst);

    // layer 1
    aggregate_kernel<<<blocks_aggr, TB>>>(h);
    gemm_tc_kernel<<<blocks_gemm, TB>>>(0, b1, p_h1, /*relu=*/1);

    // layer 2
    aggregate_kernel<<<blocks_aggr, TB>>>(p_h1);
    gemm_tc_kernel<<<blocks_gemm, TB>>>(1, b2, out, /*relu=*/0);
}

// round 15
// speedup vs baseline: 1.4444x; 1.1707x over previous
#include <cuda_runtime.h>
#include <cuda_bf16.h>
#include <cstdint>

// Problem constants (fixed by the reference)
constexpr int N_NODES = 100000;
constexpr int N_EDGES = 640000;
constexpr int D       = 128;

constexpr int SCAN_B  = 256;
constexpr int NBLK    = (N_NODES + SCAN_B - 1) / SCAN_B;   // 391

// ---------------------------------------------------------------------------
// Scratch (allocation-free: __device__ globals)
// ---------------------------------------------------------------------------
__device__ int   g_ideg_out[N_NODES];
__device__ int   g_ideg_in [N_NODES];
__device__ float g_inv_out[N_NODES];
__device__ float g_inv_in [N_NODES];
__device__ int   g_off   [N_NODES + 1];   // CSR row offsets (by dst)
__device__ int   g_cursor[N_NODES];
__device__ int   g_csr   [N_EDGES];       // src indices grouped by dst
__device__ int   g_bsum  [512];           // scan partials
// Aggregation result, pre-split to bf16 hi/lo (GEMM A operand)
__device__ __nv_bfloat16 g_ahi[(size_t)N_NODES * D];
__device__ __nv_bfloat16 g_alo[(size_t)N_NODES * D];
__device__ float g_h1 [(size_t)N_NODES * D];   // layer-1 activations (fp32)
// W split to bf16 hi/lo, stored TRANSPOSED: [n][k]
__device__ __nv_bfloat16 g_whiT[2][D * D];
__device__ __nv_bfloat16 g_wloT[2][D * D];

// ---------------------------------------------------------------------------
// Fused init (zero degree counters) + W pre-split (independent index ranges)
// ---------------------------------------------------------------------------
__global__ void init_convert_kernel(const float* __restrict__ W1,
                                    const float* __restrict__ W2) {
    int i = blockIdx.x * blockDim.x + threadIdx.x;
    if (i < N_NODES) { g_ideg_out[i] = 0; g_ideg_in[i] = 0; }
    if (i < 2 * D * D) {
        int layer = i >> 14;
        int r     = i & (D * D - 1);
        int k = r >> 7;
        int n = r & (D - 1);
        const float* W = layer ? W2 : W1;
        float w = W[k * D + n];
        __nv_bfloat16 hi = __float2bfloat16(w);
        float lo = w - __bfloat162float(hi);
        g_whiT[layer][n * D + k] = hi;
        g_wloT[layer][n * D + k] = __float2bfloat16(lo);
    }
}

__global__ void degree_kernel(const int* __restrict__ src,
                              const int* __restrict__ dst) {
    int i = blockIdx.x * blockDim.x + threadIdx.x;
    if (i < N_EDGES) {
        atomicAdd(&g_ideg_out[src[i]], 1);
        atomicAdd(&g_ideg_in [dst[i]], 1);
    }
}

// ---------------------------------------------------------------------------
// Block scan of in-degrees (shuffle-based) + fused inv-sqrt computation
// ---------------------------------------------------------------------------
__global__ void scan_block_kernel() {
    int tid  = threadIdx.x;
    int i    = blockIdx.x * SCAN_B + tid;
    int lane = tid & 31;
    int wid  = tid >> 5;

    int v = (i < N_NODES) ? g_ideg_in[i] : 0;
    if (i < N_NODES) {
        g_inv_out[i] = rsqrtf((float)max(g_ideg_out[i], 1));
        g_inv_in [i] = rsqrtf((float)max(v, 1));
    }

    int x = v;
    #pragma unroll
    for (int o = 1; o < 32; o <<= 1) {
        int t = __shfl_up_sync(0xffffffffu, x, o);
        if (lane >= o) x += t;
    }
    __shared__ int wsum[8];
    if (lane == 31) wsum[wid] = x;
    __syncthreads();
    if (wid == 0 && lane < 8) {
        int y = wsum[lane];
        #pragma unroll
        for (int o = 1; o < 8; o <<= 1) {
            int t = __shfl_up_sync(0xffu, y, o);
            if (lane >= o) y += t;
        }
        wsum[lane] = y;
    }
    __syncthreads();
    int base = wid ? wsum[wid - 1] : 0;
    int incl = x + base;
    if (i < N_NODES) g_off[i] = incl - v;          // exclusive within block
    if (tid == SCAN_B - 1) g_bsum[blockIdx.x] = incl;
}

// ---------------------------------------------------------------------------
// Fused scan finish: every block redundantly scans the 391 partials in smem,
// then applies its base to its 512 offsets + cursor init.
// ---------------------------------------------------------------------------
__global__ void scan_finish_kernel() {
    __shared__ int excl[512];
    int tid  = threadIdx.x;
    int lane = tid & 31;
    int wid  = tid >> 5;          // 16 warps

    int v = (tid < NBLK) ? g_bsum[tid] : 0;
    int x = v;
    #pragma unroll
    for (int o = 1; o < 32; o <<= 1) {
        int t = __shfl_up_sync(0xffffffffu, x, o);
        if (lane >= o) x += t;
    }
    __shared__ int ws[16];
    if (lane == 31) ws[wid] = x;
    __syncthreads();
    if (wid == 0 && lane < 16) {
        int y = ws[lane];
        #pragma unroll
        for (int o = 1; o < 16; o <<= 1) {
            int t = __shfl_up_sync(0xffffu, y, o);
            if (lane >= o) y += t;
        }
        ws[lane] = y;
    }
    __syncthreads();
    int base = wid ? ws[wid - 1] : 0;
    excl[tid] = x + base - v;    // exclusive block bases
    __syncthreads();

    int i = blockIdx.x * 512 + tid;
    if (i < N_NODES) {
        int o = g_off[i] + excl[i >> 8];
        g_off[i]    = o;
        g_cursor[i] = o;
    }
    if (i == 0) g_off[N_NODES] = N_EDGES;
}

__global__ void fill_csr_kernel(const int* __restrict__ src,
                                const int* __restrict__ dst) {
    int e = blockIdx.x * blockDim.x + threadIdx.x;
    if (e < N_EDGES) {
        int p = atomicAdd(&g_cursor[dst[e]], 1);
        g_csr[p] = src[e];
    }
}

// ---------------------------------------------------------------------------
// Pull aggregation (R8 measured-best form):
//   a[n] = inv_in[n] * sum_{s in in(n)} inv_out[s] * x[s]
// One warp per dst node; lane owns 4 contiguous features (float4 gather);
// 4-way unrolled edge loop; writes result pre-split to bf16 hi/lo.
// ---------------------------------------------------------------------------
__global__ void __launch_bounds__(256)
aggregate_kernel(const float* __restrict__ x) {
    int node = (blockIdx.x * blockDim.x + threadIdx.x) >> 5;
    int lane = threadIdx.x & 31;
    if (node >= N_NODES) return;

    int beg = g_off[node];
    int end = g_off[node + 1];
    const int c4 = lane * 4;

    float ax = 0.f, ay = 0.f, az = 0.f, aw = 0.f;
    int e  = beg;
    int n4 = beg + ((end - beg) & ~3);
    for (; e < n4; e += 4) {
        int s0 = g_csr[e];
        int s1 = g_csr[e + 1];
        int s2 = g_csr[e + 2];
        int s3 = g_csr[e + 3];
        float c0 = g_inv_out[s0];
        float c1 = g_inv_out[s1];
        float c2 = g_inv_out[s2];
        float c3 = g_inv_out[s3];
        float4 v0 = *reinterpret_cast<const float4*>(x + (size_t)s0 * D + c4);
        float4 v1 = *reinterpret_cast<const float4*>(x + (size_t)s1 * D + c4);
        float4 v2 = *reinterpret_cast<const float4*>(x + (size_t)s2 * D + c4);
        float4 v3 = *reinterpret_cast<const float4*>(x + (size_t)s3 * D + c4);
        ax += v0.x * c0 + v1.x * c1 + v2.x * c2 + v3.x * c3;
        ay += v0.y * c0 + v1.y * c1 + v2.y * c2 + v3.y * c3;
        az += v0.z * c0 + v1.z * c1 + v2.z * c2 + v3.z * c3;
        aw += v0.w * c0 + v1.w * c1 + v2.w * c2 + v3.w * c3;
    }
    for (; e < end; e++) {
        int   s0 = g_csr[e];
        float c0 = g_inv_out[s0];
        float4 v0 = *reinterpret_cast<const float4*>(x + (size_t)s0 * D + c4);
        ax += v0.x * c0; ay += v0.y * c0; az += v0.z * c0; aw += v0.w * c0;
    }

    float si = g_inv_in[node];
    ax *= si; ay *= si; az *= si; aw *= si;

    __nv_bfloat162 h01, h23, l01, l23;
    h01.x = __float2bfloat16(ax); h01.y = __float2bfloat16(ay);
    h23.x = __float2bfloat16(az); h23.y = __float2bfloat16(aw);
    l01.x = __float2bfloat16(ax - __bfloat162float(h01.x));
    l01.y = __float2bfloat16(ay - __bfloat162float(h01.y));
    l23.x = __float2bfloat16(az - __bfloat162float(h23.x));
    l23.y = __float2bfloat16(aw - __bfloat162float(h23.y));

    uint2 vh, vl;
    vh.x = *reinterpret_cast<uint32_t*>(&h01);
    vh.y = *reinterpret_cast<uint32_t*>(&h23);
    vl.x = *reinterpret_cast<uint32_t*>(&l01);
    vl.y = *reinterpret_cast<uint32_t*>(&l23);
    *reinterpret_cast<uint2*>(g_ahi + (size_t)node * D + c4) = vh;
    *reinterpret_cast<uint2*>(g_alo + (size_t)node * D + c4) = vl;
}

// ---------------------------------------------------------------------------
// Tensor-core GEMM: out = relu?( A @ W + b ), A pre-split bf16 hi/lo.
// cp.async double-buffered staging. CTA 128x128, 256 thr, warp 32x64.
// 3-product bf16 emulation.
// ---------------------------------------------------------------------------
__device__ __forceinline__ void mma_bf16(float* c, const uint32_t* a, const uint32_t* b) {
    asm volatile(
        "mma.sync.aligned.m16n8k16.row.col.f32.bf16.bf16.f32 "
        "{%0,%1,%2,%3}, {%4,%5,%6,%7}, {%8,%9}, {%0,%1,%2,%3};\n"
        : "+f"(c[0]), "+f"(c[1]), "+f"(c[2]), "+f"(c[3])
        : "r"(a[0]), "r"(a[1]), "r"(a[2]), "r"(a[3]), "r"(b[0]), "r"(b[1]));
}

__device__ __forceinline__ void cp16(uint32_t smem, const void* gptr, int src_bytes) {
    asm volatile("cp.async.ca.shared.global [%0], [%1], 16, %2;\n"
                 :: "r"(smem), "l"(gptr), "r"(src_bytes));
}

constexpr int LDSB = 40;  // padded smem stride (bf16 units), conflict-free

__global__ void __launch_bounds__(256, 2)
gemm_tc_kernel(int layer, const float* __restrict__ bias,
               float* __restrict__ out, int relu) {
    // [stage][0=Ahi,1=Alo,2=Bhi,3=Blo]
    __shared__ __align__(16) __nv_bfloat16 sm[2][4][128 * LDSB];

    const int t    = threadIdx.x;
    const int lane = t & 31;
    const int w    = t >> 5;
    const int wr   = w >> 1;
    const int wc   = w & 1;
    const int row0 = blockIdx.x * 128;

    const __nv_bfloat16* WhiT = g_whiT[layer];
    const __nv_bfloat16* WloT = g_wloT[layer];

    auto stage_chunk = [&](int c, int s) {
        const int kc = c * 32;
        #pragma unroll
        for (int j = 0; j < 2; j++) {
            int idx = t + 256 * j;        // 0..511
            int r   = idx >> 2;           // 0..127
            int k8  = (idx & 3) * 8;      // 0,8,16,24
            int gr  = row0 + r;
            int ok  = (gr < N_NODES) ? 16 : 0;
            size_t ga = (size_t)min(gr, N_NODES - 1) * D + kc + k8;
            uint32_t so = (uint32_t)((r * LDSB + k8) * 2);
            cp16((uint32_t)__cvta_generic_to_shared(&sm[s][0][0]) + so, g_ahi + ga, ok);
            cp16((uint32_t)__cvta_generic_to_shared(&sm[s][1][0]) + so, g_alo + ga, ok);
            cp16((uint32_t)__cvta_generic_to_shared(&sm[s][2][0]) + so, WhiT + r * D + kc + k8, 16);
            cp16((uint32_t)__cvta_generic_to_shared(&sm[s][3][0]) + so, WloT + r * D + kc + k8, 16);
        }
        asm volatile("cp.async.commit_group;\n");
    };

    float acc[2][8][4];
    #pragma unroll
    for (int mt = 0; mt < 2; mt++)
        #pragma unroll
        for (int nt = 0; nt < 8; nt++)
            #pragma unroll
            for (int r = 0; r < 4; r++) acc[mt][nt][r] = 0.0f;

    const int l4 = lane >> 2;
    const int l2 = (lane & 3) * 2;

    stage_chunk(0, 0);
    stage_chunk(1, 1);

    #pragma unroll
    for (int c = 0; c < 4; c++) {
        const int s = c & 1;
        if (c < 3) asm volatile("cp.async.wait_group 1;\n");
        else       asm volatile("cp.async.wait_group 0;\n");
        __syncthreads();

        const __nv_bfloat16* Ashi = sm[s][0];
        const __nv_bfloat16* Aslo = sm[s][1];
        const __nv_bfloat16* Bshi = sm[s][2];
        const __nv_bfloat16* Bslo = sm[s][3];

        #pragma unroll
        for (int kk = 0; kk < 32; kk += 16) {
            uint32_t afh[2][4], afl[2][4];
            #pragma unroll
            for (int mt = 0; mt < 2; mt++) {
                int ar = wr * 32 + mt * 16;
                int k0 = kk + l2;
                afh[mt][0] = *reinterpret_cast<const uint32_t*>(&Ashi[(ar + l4)     * LDSB + k0]);
                afh[mt][1] = *reinterpret_cast<const uint32_t*>(&Ashi[(ar + l4 + 8) * LDSB + k0]);
                afh[mt][2] = *reinterpret_cast<const uint32_t*>(&Ashi[(ar + l4)     * LDSB + k0 + 8]);
                afh[mt][3] = *reinterpret_cast<const uint32_t*>(&Ashi[(ar + l4 + 8) * LDSB + k0 + 8]);
                afl[mt][0] = *reinterpret_cast<const uint32_t*>(&Aslo[(ar + l4)     * LDSB + k0]);
                afl[mt][1] = *reinterpret_cast<const uint32_t*>(&Aslo[(ar + l4 + 8) * LDSB + k0]);
                afl[mt][2] = *reinterpret_cast<const uint32_t*>(&Aslo[(ar + l4)     * LDSB + k0 + 8]);
                afl[mt][3] = *reinterpret_cast<const uint32_t*>(&Aslo[(ar + l4 + 8) * LDSB + k0 + 8]);
            }
            #pragma unroll
            for (int nt = 0; nt < 8; nt++) {
                int bn = wc * 64 + nt * 8 + l4;
                int k0 = kk + l2;
                uint32_t bfh[2], bfl[2];
                bfh[0] = *reinterpret_cast<const uint32_t*>(&Bshi[bn * LDSB + k0]);
                bfh[1] = *reinterpret_cast<const uint32_t*>(&Bshi[bn * LDSB + k0 + 8]);
                bfl[0] = *reinterpret_cast<const uint32_t*>(&Bslo[bn * LDSB + k0]);
                bfl[1] = *reinterpret_cast<const uint32_t*>(&Bslo[bn * LDSB + k0 + 8]);
                #pragma unroll
                for (int mt = 0; mt < 2; mt++) {
                    mma_bf16(acc[mt][nt], afh[mt], bfh);
                    mma_bf16(acc[mt][nt], afh[mt], bfl);
                    mma_bf16(acc[mt][nt], afl[mt], bfh);
                }
            }
        }
        __syncthreads();
        if (c < 2) stage_chunk(c + 2, s);
    }

    #pragma unroll
    for (int mt = 0; mt < 2; mt++) {
        int gr0 = row0 + wr * 32 + mt * 16 + l4;
        int gr1 = gr0 + 8;
        #pragma unroll
        for (int nt = 0; nt < 8; nt++) {
            int col = wc * 64 + nt * 8 + l2;
            float2 bb = *reinterpret_cast<const float2*>(bias + col);
            float o0 = acc[mt][nt][0] + bb.x;
            float o1 = acc[mt][nt][1] + bb.y;
            float o2 = acc[mt][nt][2] + bb.x;
            float o3 = acc[mt][nt][3] + bb.y;
            if (relu) {
                o0 = fmaxf(o0, 0.f); o1 = fmaxf(o1, 0.f);
                o2 = fmaxf(o2, 0.f); o3 = fmaxf(o3, 0.f);
            }
            if (gr0 < N_NODES)
                *reinterpret_cast<float2*>(out + (size_t)gr0 * D + col) = make_float2(o0, o1);
            if (gr1 < N_NODES)
                *reinterpret_cast<float2*>(out + (size_t)gr1 * D + col) = make_float2(o2, o3);
        }
    }
}

// ---------------------------------------------------------------------------
// Launch sequence (graph-capturable)
// Inputs (metadata order): t, h, src, dst, W1, b1, W2, b2
// ---------------------------------------------------------------------------
extern "C" void kernel_launch(void* const* d_in, const int* in_sizes, int n_in,
                              void* d_out, int out_size) {
    const float* h   = (const float*)d_in[1];
    const int*   src = (const int*)  d_in[2];
    const int*   dst = (const int*)  d_in[3];
    const float* W1  = (const float*)d_in[4];
    const float* b1  = (const float*)d_in[5];
    const float* W2  = (const float*)d_in[6];
    const float* b2  = (const float*)d_in[7];
    float* out = (float*)d_out;

    static float* p_h1 = nullptr;
    if (!p_h1) {
        void* ph = nullptr;
        cudaGetSymbolAddress(&ph, g_h1);
        p_h1 = (float*)ph;
    }

    const int TB = 256;
    const int blocks_nodes = (N_NODES + TB - 1) / TB;        // 391
    const int blocks_edges = (N_EDGES + TB - 1) / TB;        // 2500
    const int blocks_fin   = (N_NODES + 511) / 512;          // 196
    const int blocks_aggr  = (N_NODES * 32 + TB - 1) / TB;   // 1 warp/node
    const int blocks_gemm  = (N_NODES + 127) / 128;          // 782

    // preprocessing: 5 launches
    init_convert_kernel<<<blocks_nodes, TB>>>(W1, W2);
    degree_kernel<<<blocks_edges, TB>>>(src, dst);
    scan_block_kernel<<<NBLK, SCAN_B>>>();
    scan_finish_kernel<<<blocks_fin, 512>>>();
    fill_csr_kernel<<<blocks_edges, TB>>>(src, dst);

    // layer 1
    aggregate_kernel<<<blocks_aggr, TB>>>(h);
    gemm_tc_kernel<<<blocks_gemm, TB>>>(0, b1, p_h1, /*relu=*/1);

    // layer 2
    aggregate_kernel<<<blocks_aggr, TB>>>(p_h1);
    gemm_tc_kernel<<<blocks_gemm, TB>>>(1, b2, out, /*relu=*/0);
}